// round 9
// baseline (speedup 1.0000x reference)
#include <cuda_runtime.h>

// Problem constants (fixed by the reference: B=32, d=512, T=2048)
#define B_  32
#define D_  512
#define T_  2048
#define FG  (4 * D_)        // 2048 G feature rows
#define FM  D_              // 512 m feature rows
#define FT  (FG + FM)       // 2560 total features
#define NSLICE 16
#define FS  (FT / NSLICE)   // 160 features per slice
#define TILE_T 1024         // 128 threads x 8 t each (two float4 chunks)
#define THREADS 128
#define HALF_T 512          // offset of second chunk

// Streaming load with 256B L2 promotion hint (dense pattern, read-once).
__device__ __forceinline__ float4 ldg_stream(const float* p) {
    float4 v;
    asm("ld.global.nc.L2::256B.v4.f32 {%0,%1,%2,%3}, [%4];"
        : "=f"(v.x), "=f"(v.y), "=f"(v.z), "=f"(v.w) : "l"(p));
    return v;
}

// Vector reduction into global memory (no return -> REDG, L2-side add).
__device__ __forceinline__ void redg_add4(float* p, float x, float y, float z, float w) {
    asm volatile("red.global.add.v4.f32 [%0], {%1,%2,%3,%4};"
                 :: "l"(p), "f"(x), "f"(y), "f"(z), "f"(w) : "memory");
}

// Zero the logits accumulator (= d_out, poisoned by harness each replay).
__global__ __launch_bounds__(512)
void zero_kernel(float4* __restrict__ out) {
    out[blockIdx.x * 512 + threadIdx.x] = make_float4(0.f, 0.f, 0.f, 0.f);
}

// min-blocks=8 forces <=64 regs/thread -> 8 CTAs/SM -> all 1024 blocks
// resident in a single wave (no tail wave).
__global__ __launch_bounds__(THREADS, 8)
void dot_kernel(const float* __restrict__ G,
                const float* __restrict__ m1,
                const float* __restrict__ m2,
                const float* __restrict__ wp1,
                const float* __restrict__ wp2,
                float* __restrict__ logits) {
    __shared__ float w1s[FS];
    __shared__ float w2s[FS];

    const int b     = blockIdx.y;
    const int slice = blockIdx.z;
    const int fbase = slice * FS;

    for (int i = threadIdx.x; i < FS; i += THREADS) {
        w1s[i] = wp1[fbase + i];
        w2s[i] = wp2[fbase + i];
    }
    __syncthreads();

    // Two independent t-chunks per thread: t0 and t0 + HALF_T
    const int t0 = blockIdx.x * TILE_T + threadIdx.x * 4;

    float a1ax=0.f,a1ay=0.f,a1az=0.f,a1aw=0.f, a1bx=0.f,a1by=0.f,a1bz=0.f,a1bw=0.f;
    float a2ax=0.f,a2ay=0.f,a2az=0.f,a2aw=0.f, a2bx=0.f,a2by=0.f,a2bz=0.f,a2bw=0.f;

    // --- G portion of this slice ---
    const int fG_end = (fbase + FS < FG) ? (fbase + FS) : FG;
    const float* Gb = G + (size_t)b * FG * T_ + t0;
#pragma unroll 4
    for (int f = fbase; f < fG_end; ++f) {
        const float* row = Gb + (size_t)f * T_;
        float4 ga = ldg_stream(row);
        float4 gb = ldg_stream(row + HALF_T);
        float w1 = w1s[f - fbase];
        float w2 = w2s[f - fbase];
        a1ax = fmaf(ga.x, w1, a1ax);  a2ax = fmaf(ga.x, w2, a2ax);
        a1ay = fmaf(ga.y, w1, a1ay);  a2ay = fmaf(ga.y, w2, a2ay);
        a1az = fmaf(ga.z, w1, a1az);  a2az = fmaf(ga.z, w2, a2az);
        a1aw = fmaf(ga.w, w1, a1aw);  a2aw = fmaf(ga.w, w2, a2aw);
        a1bx = fmaf(gb.x, w1, a1bx);  a2bx = fmaf(gb.x, w2, a2bx);
        a1by = fmaf(gb.y, w1, a1by);  a2by = fmaf(gb.y, w2, a2by);
        a1bz = fmaf(gb.z, w1, a1bz);  a2bz = fmaf(gb.z, w2, a2bz);
        a1bw = fmaf(gb.w, w1, a1bw);  a2bw = fmaf(gb.w, w2, a2bw);
    }

    // --- m portion of this slice ---
    const int fM_beg = (fbase > FG) ? fbase : FG;
    const int fM_end = fbase + FS;
    const float* M1b = m1 + (size_t)b * FM * T_ + t0;
    const float* M2b = m2 + (size_t)b * FM * T_ + t0;
#pragma unroll 4
    for (int f = fM_beg; f < fM_end; ++f) {
        const int fm = f - FG;
        const float* r1 = M1b + (size_t)fm * T_;
        const float* r2 = M2b + (size_t)fm * T_;
        float4 v1a = ldg_stream(r1);
        float4 v1b = ldg_stream(r1 + HALF_T);
        float4 v2a = ldg_stream(r2);
        float4 v2b = ldg_stream(r2 + HALF_T);
        float w1 = w1s[f - fbase];
        float w2 = w2s[f - fbase];
        a1ax = fmaf(v1a.x, w1, a1ax);  a2ax = fmaf(v2a.x, w2, a2ax);
        a1ay = fmaf(v1a.y, w1, a1ay);  a2ay = fmaf(v2a.y, w2, a2ay);
        a1az = fmaf(v1a.z, w1, a1az);  a2az = fmaf(v2a.z, w2, a2az);
        a1aw = fmaf(v1a.w, w1, a1aw);  a2aw = fmaf(v2a.w, w2, a2aw);
        a1bx = fmaf(v1b.x, w1, a1bx);  a2bx = fmaf(v2b.x, w2, a2bx);
        a1by = fmaf(v1b.y, w1, a1by);  a2by = fmaf(v2b.y, w2, a2by);
        a1bz = fmaf(v1b.z, w1, a1bz);  a2bz = fmaf(v2b.z, w2, a2bz);
        a1bw = fmaf(v1b.w, w1, a1bw);  a2bw = fmaf(v2b.w, w2, a2bw);
    }

    // Accumulate directly into logits (= d_out): [b][head][t]
    float* L1 = logits + ((size_t)b * 2 + 0) * T_ + t0;
    float* L2 = logits + ((size_t)b * 2 + 1) * T_ + t0;
    redg_add4(L1,          a1ax, a1ay, a1az, a1aw);
    redg_add4(L1 + HALF_T, a1bx, a1by, a1bz, a1bw);
    redg_add4(L2,          a2ax, a2ay, a2az, a2aw);
    redg_add4(L2 + HALF_T, a2bx, a2by, a2bz, a2bw);
}

// In-place softmax over T for each (b, head). Reads the L2-hot logits
// accumulated by dot_kernel, writes normalized probs back to the same buffer.
__global__ __launch_bounds__(512)
void softmax_kernel(float* __restrict__ out) {
    const int head = blockIdx.x;
    const int b    = blockIdx.y;
    const int tid  = threadIdx.x;
    float* row = out + ((size_t)b * 2 + head) * T_;

    float4 q = *(const float4*)&row[tid * 4];

    // --- block max ---
    float mx = fmaxf(fmaxf(q.x, q.y), fmaxf(q.z, q.w));
#pragma unroll
    for (int o = 16; o > 0; o >>= 1)
        mx = fmaxf(mx, __shfl_xor_sync(0xffffffffu, mx, o));
    __shared__ float red[16];
    const int wid = tid >> 5, lid = tid & 31;
    if (lid == 0) red[wid] = mx;
    __syncthreads();
    if (wid == 0) {
        float r = red[lid & 15];
#pragma unroll
        for (int o = 8; o > 0; o >>= 1)
            r = fmaxf(r, __shfl_xor_sync(0xffffffffu, r, o));
        if (lid == 0) red[0] = r;
    }
    __syncthreads();
    mx = red[0];
    __syncthreads();

    // --- exp + block sum ---
    q.x = __expf(q.x - mx); q.y = __expf(q.y - mx);
    q.z = __expf(q.z - mx); q.w = __expf(q.w - mx);
    float sum = q.x + q.y + q.z + q.w;
#pragma unroll
    for (int o = 16; o > 0; o >>= 1)
        sum += __shfl_xor_sync(0xffffffffu, sum, o);
    if (lid == 0) red[wid] = sum;
    __syncthreads();
    if (wid == 0) {
        float r = red[lid & 15];
#pragma unroll
        for (int o = 8; o > 0; o >>= 1)
            r += __shfl_xor_sync(0xffffffffu, r, o);
        if (lid == 0) red[0] = r;
    }
    __syncthreads();
    const float inv = 1.0f / red[0];

    *(float4*)&row[tid * 4] = make_float4(q.x * inv, q.y * inv, q.z * inv, q.w * inv);
}

extern "C" void kernel_launch(void* const* d_in, const int* in_sizes, int n_in,
                              void* d_out, int out_size) {
    const float* G   = (const float*)d_in[0];
    const float* m1  = (const float*)d_in[1];
    const float* m2  = (const float*)d_in[2];
    const float* wp1 = (const float*)d_in[3];
    const float* wp2 = (const float*)d_in[4];
    float* out = (float*)d_out;

    // out_size = 32*2*2048 = 131072 floats = 32768 float4 -> 64 blocks x 512
    zero_kernel<<<64, 512>>>((float4*)out);

    dim3 grid(T_ / TILE_T, B_, NSLICE);   // (2, 32, 16) = 1024 blocks
    dot_kernel<<<grid, THREADS>>>(G, m1, m2, wp1, wp2, out);

    softmax_kernel<<<dim3(2, B_), 512>>>(out);
}

// round 11
// speedup vs baseline: 1.0154x; 1.0154x over previous
#include <cuda_runtime.h>

// Problem constants (fixed by the reference: B=32, d=512, T=2048)
#define B_  32
#define D_  512
#define T_  2048
#define FG  (4 * D_)        // 2048 G feature rows
#define FM  D_              // 512 m feature rows
#define FT  (FG + FM)       // 2560 total features
#define NSLICE 16
#define FS  (FT / NSLICE)   // 160 features per slice
#define TILE_T 1024         // 128 threads x 8 t each (two float4 chunks)
#define THREADS 128
#define HALF_T 512          // offset of second chunk

// Logits accumulator: [b][head][t], 512 KB. Zero-initialized at module load;
// softmax_kernel re-zeroes it after consuming, so every kernel_launch call
// (and every graph replay) sees it as all-zeros. No zero kernel needed.
__device__ float g_logits[B_ * 2 * T_];

// Streaming load with 256B L2 promotion hint (dense pattern, read-once).
__device__ __forceinline__ float4 ldg_stream(const float* p) {
    float4 v;
    asm("ld.global.nc.L2::256B.v4.f32 {%0,%1,%2,%3}, [%4];"
        : "=f"(v.x), "=f"(v.y), "=f"(v.z), "=f"(v.w) : "l"(p));
    return v;
}

// Vector reduction into global memory (no return -> REDG, L2-side add).
__device__ __forceinline__ void redg_add4(float* p, float x, float y, float z, float w) {
    asm volatile("red.global.add.v4.f32 [%0], {%1,%2,%3,%4};"
                 :: "l"(p), "f"(x), "f"(y), "f"(z), "f"(w) : "memory");
}

// min-blocks=8 forces <=64 regs/thread -> 8 CTAs/SM -> all 1024 blocks
// resident in a single wave (no tail wave).
__global__ __launch_bounds__(THREADS, 8)
void dot_kernel(const float* __restrict__ G,
                const float* __restrict__ m1,
                const float* __restrict__ m2,
                const float* __restrict__ wp1,
                const float* __restrict__ wp2) {
    __shared__ float w1s[FS];
    __shared__ float w2s[FS];

    const int b     = blockIdx.y;
    const int slice = blockIdx.z;
    const int fbase = slice * FS;

    for (int i = threadIdx.x; i < FS; i += THREADS) {
        w1s[i] = wp1[fbase + i];
        w2s[i] = wp2[fbase + i];
    }
    __syncthreads();

    // Two independent t-chunks per thread: t0 and t0 + HALF_T
    const int t0 = blockIdx.x * TILE_T + threadIdx.x * 4;

    float a1ax=0.f,a1ay=0.f,a1az=0.f,a1aw=0.f, a1bx=0.f,a1by=0.f,a1bz=0.f,a1bw=0.f;
    float a2ax=0.f,a2ay=0.f,a2az=0.f,a2aw=0.f, a2bx=0.f,a2by=0.f,a2bz=0.f,a2bw=0.f;

    // --- G portion of this slice ---
    const int fG_end = (fbase + FS < FG) ? (fbase + FS) : FG;
    const float* Gb = G + (size_t)b * FG * T_ + t0;
#pragma unroll 4
    for (int f = fbase; f < fG_end; ++f) {
        const float* row = Gb + (size_t)f * T_;
        float4 ga = ldg_stream(row);
        float4 gb = ldg_stream(row + HALF_T);
        float w1 = w1s[f - fbase];
        float w2 = w2s[f - fbase];
        a1ax = fmaf(ga.x, w1, a1ax);  a2ax = fmaf(ga.x, w2, a2ax);
        a1ay = fmaf(ga.y, w1, a1ay);  a2ay = fmaf(ga.y, w2, a2ay);
        a1az = fmaf(ga.z, w1, a1az);  a2az = fmaf(ga.z, w2, a2az);
        a1aw = fmaf(ga.w, w1, a1aw);  a2aw = fmaf(ga.w, w2, a2aw);
        a1bx = fmaf(gb.x, w1, a1bx);  a2bx = fmaf(gb.x, w2, a2bx);
        a1by = fmaf(gb.y, w1, a1by);  a2by = fmaf(gb.y, w2, a2by);
        a1bz = fmaf(gb.z, w1, a1bz);  a2bz = fmaf(gb.z, w2, a2bz);
        a1bw = fmaf(gb.w, w1, a1bw);  a2bw = fmaf(gb.w, w2, a2bw);
    }

    // --- m portion of this slice ---
    const int fM_beg = (fbase > FG) ? fbase : FG;
    const int fM_end = fbase + FS;
    const float* M1b = m1 + (size_t)b * FM * T_ + t0;
    const float* M2b = m2 + (size_t)b * FM * T_ + t0;
#pragma unroll 4
    for (int f = fM_beg; f < fM_end; ++f) {
        const int fm = f - FG;
        const float* r1 = M1b + (size_t)fm * T_;
        const float* r2 = M2b + (size_t)fm * T_;
        float4 v1a = ldg_stream(r1);
        float4 v1b = ldg_stream(r1 + HALF_T);
        float4 v2a = ldg_stream(r2);
        float4 v2b = ldg_stream(r2 + HALF_T);
        float w1 = w1s[f - fbase];
        float w2 = w2s[f - fbase];
        a1ax = fmaf(v1a.x, w1, a1ax);  a2ax = fmaf(v2a.x, w2, a2ax);
        a1ay = fmaf(v1a.y, w1, a1ay);  a2ay = fmaf(v2a.y, w2, a2ay);
        a1az = fmaf(v1a.z, w1, a1az);  a2az = fmaf(v2a.z, w2, a2az);
        a1aw = fmaf(v1a.w, w1, a1aw);  a2aw = fmaf(v2a.w, w2, a2aw);
        a1bx = fmaf(v1b.x, w1, a1bx);  a2bx = fmaf(v2b.x, w2, a2bx);
        a1by = fmaf(v1b.y, w1, a1by);  a2by = fmaf(v2b.y, w2, a2by);
        a1bz = fmaf(v1b.z, w1, a1bz);  a2bz = fmaf(v2b.z, w2, a2bz);
        a1bw = fmaf(v1b.w, w1, a1bw);  a2bw = fmaf(v2b.w, w2, a2bw);
    }

    // Accumulate directly into the logits scratch: [b][head][t]
    float* L1 = g_logits + ((size_t)b * 2 + 0) * T_ + t0;
    float* L2 = g_logits + ((size_t)b * 2 + 1) * T_ + t0;
    redg_add4(L1,          a1ax, a1ay, a1az, a1aw);
    redg_add4(L1 + HALF_T, a1bx, a1by, a1bz, a1bw);
    redg_add4(L2,          a2ax, a2ay, a2az, a2aw);
    redg_add4(L2 + HALF_T, a2bx, a2by, a2bz, a2bw);
}

// Softmax over T for each (b, head). Reads the L2-hot logits scratch, writes
// normalized probs to d_out, then re-zeroes its scratch row so the next
// kernel_launch call / graph replay starts from a clean accumulator.
__global__ __launch_bounds__(512)
void softmax_kernel(float* __restrict__ out) {
    const int head = blockIdx.x;
    const int b    = blockIdx.y;
    const int tid  = threadIdx.x;
    float* srow = g_logits + ((size_t)b * 2 + head) * T_;

    float4 q = *(const float4*)&srow[tid * 4];

    // --- block max ---
    float mx = fmaxf(fmaxf(q.x, q.y), fmaxf(q.z, q.w));
#pragma unroll
    for (int o = 16; o > 0; o >>= 1)
        mx = fmaxf(mx, __shfl_xor_sync(0xffffffffu, mx, o));
    __shared__ float red[16];
    const int wid = tid >> 5, lid = tid & 31;
    if (lid == 0) red[wid] = mx;
    __syncthreads();
    if (wid == 0) {
        float r = red[lid & 15];
#pragma unroll
        for (int o = 8; o > 0; o >>= 1)
            r = fmaxf(r, __shfl_xor_sync(0xffffffffu, r, o));
        if (lid == 0) red[0] = r;
    }
    __syncthreads();
    mx = red[0];
    __syncthreads();

    // --- exp + block sum ---
    q.x = __expf(q.x - mx); q.y = __expf(q.y - mx);
    q.z = __expf(q.z - mx); q.w = __expf(q.w - mx);
    float sum = q.x + q.y + q.z + q.w;
#pragma unroll
    for (int o = 16; o > 0; o >>= 1)
        sum += __shfl_xor_sync(0xffffffffu, sum, o);
    if (lid == 0) red[wid] = sum;
    __syncthreads();
    if (wid == 0) {
        float r = red[lid & 15];
#pragma unroll
        for (int o = 8; o > 0; o >>= 1)
            r += __shfl_xor_sync(0xffffffffu, r, o);
        if (lid == 0) red[0] = r;
    }
    __syncthreads();
    const float inv = 1.0f / red[0];

    *(float4*)&out[((size_t)b * 2 + head) * T_ + tid * 4] =
        make_float4(q.x * inv, q.y * inv, q.z * inv, q.w * inv);

    // Restore the zero-invariant for the next call/replay.
    *(float4*)&srow[tid * 4] = make_float4(0.f, 0.f, 0.f, 0.f);
}

extern "C" void kernel_launch(void* const* d_in, const int* in_sizes, int n_in,
                              void* d_out, int out_size) {
    const float* G   = (const float*)d_in[0];
    const float* m1  = (const float*)d_in[1];
    const float* m2  = (const float*)d_in[2];
    const float* wp1 = (const float*)d_in[3];
    const float* wp2 = (const float*)d_in[4];
    float* out = (float*)d_out;

    dim3 grid(T_ / TILE_T, B_, NSLICE);   // (2, 32, 16) = 1024 blocks
    dot_kernel<<<grid, THREADS>>>(G, m1, m2, wp1, wp2);

    softmax_kernel<<<dim3(2, B_), 512>>>(out);
}

// round 14
// speedup vs baseline: 1.1050x; 1.0883x over previous
#include <cuda_runtime.h>

// Problem constants (fixed by the reference: B=32, d=512, T=2048)
#define B_  32
#define D_  512
#define T_  2048
#define FG  (4 * D_)        // 2048 G feature rows
#define FM  D_              // 512 m feature rows
#define FT  (FG + FM)       // 2560 total features
#define NSLICE 16
#define FS  (FT / NSLICE)   // 160 features per slice
#define TILE_T 1024         // 128 threads x 8 t each (two float4 chunks)
#define THREADS 128
#define HALF_T 512          // offset of second chunk
#define BLOCKS_PER_B ((T_ / TILE_T) * NSLICE)   // 32 contributors per batch

// Logits accumulator: [b][head][t], 512 KB. Zero-initialized at module load;
// the fused softmax tail re-zeroes consumed rows, so every kernel_launch call
// (and every graph replay) sees it as all-zeros.
__device__ float g_logits[B_ * 2 * T_];
// Completion counters, one per batch. Reset by the tail block each call.
__device__ int g_count[B_];

// Streaming load with 256B L2 promotion hint (dense pattern, read-once).
__device__ __forceinline__ float4 ldg_stream(const float* p) {
    float4 v;
    asm("ld.global.nc.L2::256B.v4.f32 {%0,%1,%2,%3}, [%4];"
        : "=f"(v.x), "=f"(v.y), "=f"(v.z), "=f"(v.w) : "l"(p));
    return v;
}

// L2-direct load (bypass L1) for reading REDG-accumulated data.
__device__ __forceinline__ float4 ldg_cg4(const float* p) {
    float4 v;
    asm volatile("ld.global.cg.v4.f32 {%0,%1,%2,%3}, [%4];"
                 : "=f"(v.x), "=f"(v.y), "=f"(v.z), "=f"(v.w) : "l"(p) : "memory");
    return v;
}

// Vector reduction into global memory (no return -> REDG, L2-side add).
__device__ __forceinline__ void redg_add4(float* p, float x, float y, float z, float w) {
    asm volatile("red.global.add.v4.f32 [%0], {%1,%2,%3,%4};"
                 :: "l"(p), "f"(x), "f"(y), "f"(z), "f"(w) : "memory");
}

// min-blocks=8 -> <=64 regs -> 8 CTAs/SM -> all 1024 blocks in one wave.
__global__ __launch_bounds__(THREADS, 8)
void dot_kernel(const float* __restrict__ G,
                const float* __restrict__ m1,
                const float* __restrict__ m2,
                const float* __restrict__ wp1,
                const float* __restrict__ wp2,
                float* __restrict__ out) {
    __shared__ float w1s[FS];
    __shared__ float w2s[FS];

    const int b     = blockIdx.y;
    const int slice = blockIdx.z;
    const int fbase = slice * FS;

    for (int i = threadIdx.x; i < FS; i += THREADS) {
        w1s[i] = wp1[fbase + i];
        w2s[i] = wp2[fbase + i];
    }
    __syncthreads();

    const int t0 = blockIdx.x * TILE_T + threadIdx.x * 4;

    float a1ax=0.f,a1ay=0.f,a1az=0.f,a1aw=0.f, a1bx=0.f,a1by=0.f,a1bz=0.f,a1bw=0.f;
    float a2ax=0.f,a2ay=0.f,a2az=0.f,a2aw=0.f, a2bx=0.f,a2by=0.f,a2bz=0.f,a2bw=0.f;

    // --- G portion of this slice ---
    const int fG_end = (fbase + FS < FG) ? (fbase + FS) : FG;
    const float* Gb = G + (size_t)b * FG * T_ + t0;
#pragma unroll 4
    for (int f = fbase; f < fG_end; ++f) {
        const float* row = Gb + (size_t)f * T_;
        float4 ga = ldg_stream(row);
        float4 gb = ldg_stream(row + HALF_T);
        float w1 = w1s[f - fbase];
        float w2 = w2s[f - fbase];
        a1ax = fmaf(ga.x, w1, a1ax);  a2ax = fmaf(ga.x, w2, a2ax);
        a1ay = fmaf(ga.y, w1, a1ay);  a2ay = fmaf(ga.y, w2, a2ay);
        a1az = fmaf(ga.z, w1, a1az);  a2az = fmaf(ga.z, w2, a2az);
        a1aw = fmaf(ga.w, w1, a1aw);  a2aw = fmaf(ga.w, w2, a2aw);
        a1bx = fmaf(gb.x, w1, a1bx);  a2bx = fmaf(gb.x, w2, a2bx);
        a1by = fmaf(gb.y, w1, a1by);  a2by = fmaf(gb.y, w2, a2by);
        a1bz = fmaf(gb.z, w1, a1bz);  a2bz = fmaf(gb.z, w2, a2bz);
        a1bw = fmaf(gb.w, w1, a1bw);  a2bw = fmaf(gb.w, w2, a2bw);
    }

    // --- m portion of this slice ---
    const int fM_beg = (fbase > FG) ? fbase : FG;
    const int fM_end = fbase + FS;
    const float* M1b = m1 + (size_t)b * FM * T_ + t0;
    const float* M2b = m2 + (size_t)b * FM * T_ + t0;
#pragma unroll 4
    for (int f = fM_beg; f < fM_end; ++f) {
        const int fm = f - FG;
        const float* r1 = M1b + (size_t)fm * T_;
        const float* r2 = M2b + (size_t)fm * T_;
        float4 v1a = ldg_stream(r1);
        float4 v1b = ldg_stream(r1 + HALF_T);
        float4 v2a = ldg_stream(r2);
        float4 v2b = ldg_stream(r2 + HALF_T);
        float w1 = w1s[f - fbase];
        float w2 = w2s[f - fbase];
        a1ax = fmaf(v1a.x, w1, a1ax);  a2ax = fmaf(v2a.x, w2, a2ax);
        a1ay = fmaf(v1a.y, w1, a1ay);  a2ay = fmaf(v2a.y, w2, a2ay);
        a1az = fmaf(v1a.z, w1, a1az);  a2az = fmaf(v2a.z, w2, a2az);
        a1aw = fmaf(v1a.w, w1, a1aw);  a2aw = fmaf(v2a.w, w2, a2aw);
        a1bx = fmaf(v1b.x, w1, a1bx);  a2bx = fmaf(v2b.x, w2, a2bx);
        a1by = fmaf(v1b.y, w1, a1by);  a2by = fmaf(v2b.y, w2, a2by);
        a1bz = fmaf(v1b.z, w1, a1bz);  a2bz = fmaf(v2b.z, w2, a2bz);
        a1bw = fmaf(v1b.w, w1, a1bw);  a2bw = fmaf(v2b.w, w2, a2bw);
    }

    // Accumulate into the logits scratch: [b][head][t]
    float* L1 = g_logits + ((size_t)b * 2 + 0) * T_ + t0;
    float* L2 = g_logits + ((size_t)b * 2 + 1) * T_ + t0;
    redg_add4(L1,          a1ax, a1ay, a1az, a1aw);
    redg_add4(L1 + HALF_T, a1bx, a1by, a1bz, a1bw);
    redg_add4(L2,          a2ax, a2ay, a2az, a2aw);
    redg_add4(L2 + HALF_T, a2bx, a2by, a2bz, a2bw);

    // ---- last-block-done fused softmax tail ----
    // Release: every thread fences its own REDGs, THEN the barrier guarantees
    // all 128 threads' fenced stores precede thread 0's signal.
    __threadfence();
    __syncthreads();
    __shared__ int s_last;
    if (threadIdx.x == 0)
        s_last = (atomicAdd(&g_count[b], 1) == BLOCKS_PER_B - 1);
    __syncthreads();
    if (!s_last) return;
    __threadfence();   // acquire: all 32 blocks' contributions now visible

    const int tid = threadIdx.x;
    const int wid = tid >> 5, lid = tid & 31;
    __shared__ float red[4];

    for (int head = 0; head < 2; ++head) {
        float* srow = g_logits + ((size_t)b * 2 + head) * T_;
        float* orow = out      + ((size_t)b * 2 + head) * T_;

        float4 v[4];
#pragma unroll
        for (int c = 0; c < 4; ++c)
            v[c] = ldg_cg4(&srow[c * 512 + tid * 4]);   // L2-direct

        // block max (4 warps)
        float mx = -3.402823466e+38f;
#pragma unroll
        for (int c = 0; c < 4; ++c)
            mx = fmaxf(mx, fmaxf(fmaxf(v[c].x, v[c].y), fmaxf(v[c].z, v[c].w)));
#pragma unroll
        for (int o = 16; o > 0; o >>= 1)
            mx = fmaxf(mx, __shfl_xor_sync(0xffffffffu, mx, o));
        if (lid == 0) red[wid] = mx;
        __syncthreads();
        mx = fmaxf(fmaxf(red[0], red[1]), fmaxf(red[2], red[3]));
        __syncthreads();

        // exp + block sum
        float sum = 0.f;
#pragma unroll
        for (int c = 0; c < 4; ++c) {
            v[c].x = __expf(v[c].x - mx); v[c].y = __expf(v[c].y - mx);
            v[c].z = __expf(v[c].z - mx); v[c].w = __expf(v[c].w - mx);
            sum += v[c].x + v[c].y + v[c].z + v[c].w;
        }
#pragma unroll
        for (int o = 16; o > 0; o >>= 1)
            sum += __shfl_xor_sync(0xffffffffu, sum, o);
        if (lid == 0) red[wid] = sum;
        __syncthreads();
        const float inv = 1.0f / (red[0] + red[1] + red[2] + red[3]);
        __syncthreads();

#pragma unroll
        for (int c = 0; c < 4; ++c) {
            *(float4*)&orow[c * 512 + tid * 4] =
                make_float4(v[c].x * inv, v[c].y * inv, v[c].z * inv, v[c].w * inv);
            // restore zero-invariant for the next call/replay
            *(float4*)&srow[c * 512 + tid * 4] = make_float4(0.f, 0.f, 0.f, 0.f);
        }
    }

    if (tid == 0) g_count[b] = 0;   // reset counter for next call/replay
}

extern "C" void kernel_launch(void* const* d_in, const int* in_sizes, int n_in,
                              void* d_out, int out_size) {
    const float* G   = (const float*)d_in[0];
    const float* m1  = (const float*)d_in[1];
    const float* m2  = (const float*)d_in[2];
    const float* wp1 = (const float*)d_in[3];
    const float* wp2 = (const float*)d_in[4];
    float* out = (float*)d_out;

    dim3 grid(T_ / TILE_T, B_, NSLICE);   // (2, 32, 16) = 1024 blocks
    dot_kernel<<<grid, THREADS>>>(G, m1, m2, wp1, wp2, out);
}

// round 16
// speedup vs baseline: 1.1071x; 1.0019x over previous
#include <cuda_runtime.h>

// Problem constants (fixed by the reference: B=32, d=512, T=2048)
#define B_  32
#define D_  512
#define T_  2048
#define FG  (4 * D_)        // 2048 G feature rows
#define FM  D_              // 512 m feature rows
#define FT  (FG + FM)       // 2560 total features
#define NSLICE 16
#define FS  (FT / NSLICE)   // 160 features per slice
#define TILE_T 1024         // 128 threads x 8 t each (two float4 chunks)
#define THREADS 128
#define HALF_T 512          // offset of second chunk
#define BLOCKS_PER_B ((T_ / TILE_T) * NSLICE)   // 32 contributors per batch

// Logits accumulator: [b][head][t], 512 KB. Zero-initialized at module load;
// the fused softmax tail re-zeroes consumed rows, so every kernel_launch call
// (and every graph replay) sees it as all-zeros.
__device__ float g_logits[B_ * 2 * T_];
// Completion counters, one per batch. Reset by the tail block each call.
__device__ int g_count[B_];

// Streaming load with 256B L2 promotion hint (dense pattern, read-once).
__device__ __forceinline__ float4 ldg_stream(const float* p) {
    float4 v;
    asm("ld.global.nc.L2::256B.v4.f32 {%0,%1,%2,%3}, [%4];"
        : "=f"(v.x), "=f"(v.y), "=f"(v.z), "=f"(v.w) : "l"(p));
    return v;
}

// L2-direct load (bypass L1) for reading REDG-accumulated data.
__device__ __forceinline__ float4 ldg_cg4(const float* p) {
    float4 v;
    asm volatile("ld.global.cg.v4.f32 {%0,%1,%2,%3}, [%4];"
                 : "=f"(v.x), "=f"(v.y), "=f"(v.z), "=f"(v.w) : "l"(p) : "memory");
    return v;
}

// Vector reduction into global memory (no return -> REDG, L2-side add).
__device__ __forceinline__ void redg_add4(float* p, float x, float y, float z, float w) {
    asm volatile("red.global.add.v4.f32 [%0], {%1,%2,%3,%4};"
                 :: "l"(p), "f"(x), "f"(y), "f"(z), "f"(w) : "memory");
}

// min-blocks=8 -> <=64 regs -> 8 CTAs/SM -> all 1024 blocks in one wave.
__global__ __launch_bounds__(THREADS, 8)
void dot_kernel(const float* __restrict__ G,
                const float* __restrict__ m1,
                const float* __restrict__ m2,
                const float* __restrict__ wp1,
                const float* __restrict__ wp2,
                float* __restrict__ out) {
    __shared__ float w1s[FS];
    __shared__ float w2s[FS];

    const int b     = blockIdx.y;
    const int slice = blockIdx.z;
    const int fbase = slice * FS;

    const int t0 = blockIdx.x * TILE_T + threadIdx.x * 4;

    const int fG_end = (fbase + FS < FG) ? (fbase + FS) : FG;
    const int fM_beg = (fbase > FG) ? fbase : FG;
    const int fM_end = fbase + FS;
    const bool gstart = (fbase < FG);

    const float* Gb  = G  + (size_t)b * FG * T_ + t0;
    const float* M1b = m1 + (size_t)b * FM * T_ + t0;
    const float* M2b = m2 + (size_t)b * FM * T_ + t0;

    // ---- prefetch first rows BEFORE the weight-staging barrier ----
    // (row addresses are weight-independent; hides the staging+barrier latency)
    float4 pf0, pf1, pf2, pf3, pf4, pf5, pf6, pf7;
    if (gstart) {
        const float* r0 = Gb + (size_t)(fbase + 0) * T_;
        const float* r1 = Gb + (size_t)(fbase + 1) * T_;
        const float* r2 = Gb + (size_t)(fbase + 2) * T_;
        const float* r3 = Gb + (size_t)(fbase + 3) * T_;
        pf0 = ldg_stream(r0); pf1 = ldg_stream(r0 + HALF_T);
        pf2 = ldg_stream(r1); pf3 = ldg_stream(r1 + HALF_T);
        pf4 = ldg_stream(r2); pf5 = ldg_stream(r2 + HALF_T);
        pf6 = ldg_stream(r3); pf7 = ldg_stream(r3 + HALF_T);
    } else {
        const int fm = fbase - FG;
        const float* r1 = M1b + (size_t)fm * T_;
        const float* r2 = M2b + (size_t)fm * T_;
        const float* r3 = M1b + (size_t)(fm + 1) * T_;
        const float* r4 = M2b + (size_t)(fm + 1) * T_;
        pf0 = ldg_stream(r1); pf1 = ldg_stream(r1 + HALF_T);
        pf2 = ldg_stream(r2); pf3 = ldg_stream(r2 + HALF_T);
        pf4 = ldg_stream(r3); pf5 = ldg_stream(r3 + HALF_T);
        pf6 = ldg_stream(r4); pf7 = ldg_stream(r4 + HALF_T);
    }

    for (int i = threadIdx.x; i < FS; i += THREADS) {
        w1s[i] = wp1[fbase + i];
        w2s[i] = wp2[fbase + i];
    }
    __syncthreads();

    float a1ax=0.f,a1ay=0.f,a1az=0.f,a1aw=0.f, a1bx=0.f,a1by=0.f,a1bz=0.f,a1bw=0.f;
    float a2ax=0.f,a2ay=0.f,a2az=0.f,a2aw=0.f, a2bx=0.f,a2by=0.f,a2bz=0.f,a2bw=0.f;

    int gBeg = fbase, mBeg = fM_beg;
    if (gstart) {
        // consume 4 prefetched G rows
        float w1, w2;
        w1 = w1s[0]; w2 = w2s[0];
        a1ax=fmaf(pf0.x,w1,a1ax); a2ax=fmaf(pf0.x,w2,a2ax);
        a1ay=fmaf(pf0.y,w1,a1ay); a2ay=fmaf(pf0.y,w2,a2ay);
        a1az=fmaf(pf0.z,w1,a1az); a2az=fmaf(pf0.z,w2,a2az);
        a1aw=fmaf(pf0.w,w1,a1aw); a2aw=fmaf(pf0.w,w2,a2aw);
        a1bx=fmaf(pf1.x,w1,a1bx); a2bx=fmaf(pf1.x,w2,a2bx);
        a1by=fmaf(pf1.y,w1,a1by); a2by=fmaf(pf1.y,w2,a2by);
        a1bz=fmaf(pf1.z,w1,a1bz); a2bz=fmaf(pf1.z,w2,a2bz);
        a1bw=fmaf(pf1.w,w1,a1bw); a2bw=fmaf(pf1.w,w2,a2bw);
        w1 = w1s[1]; w2 = w2s[1];
        a1ax=fmaf(pf2.x,w1,a1ax); a2ax=fmaf(pf2.x,w2,a2ax);
        a1ay=fmaf(pf2.y,w1,a1ay); a2ay=fmaf(pf2.y,w2,a2ay);
        a1az=fmaf(pf2.z,w1,a1az); a2az=fmaf(pf2.z,w2,a2az);
        a1aw=fmaf(pf2.w,w1,a1aw); a2aw=fmaf(pf2.w,w2,a2aw);
        a1bx=fmaf(pf3.x,w1,a1bx); a2bx=fmaf(pf3.x,w2,a2bx);
        a1by=fmaf(pf3.y,w1,a1by); a2by=fmaf(pf3.y,w2,a2by);
        a1bz=fmaf(pf3.z,w1,a1bz); a2bz=fmaf(pf3.z,w2,a2bz);
        a1bw=fmaf(pf3.w,w1,a1bw); a2bw=fmaf(pf3.w,w2,a2bw);
        w1 = w1s[2]; w2 = w2s[2];
        a1ax=fmaf(pf4.x,w1,a1ax); a2ax=fmaf(pf4.x,w2,a2ax);
        a1ay=fmaf(pf4.y,w1,a1ay); a2ay=fmaf(pf4.y,w2,a2ay);
        a1az=fmaf(pf4.z,w1,a1az); a2az=fmaf(pf4.z,w2,a2az);
        a1aw=fmaf(pf4.w,w1,a1aw); a2aw=fmaf(pf4.w,w2,a2aw);
        a1bx=fmaf(pf5.x,w1,a1bx); a2bx=fmaf(pf5.x,w2,a2bx);
        a1by=fmaf(pf5.y,w1,a1by); a2by=fmaf(pf5.y,w2,a2by);
        a1bz=fmaf(pf5.z,w1,a1bz); a2bz=fmaf(pf5.z,w2,a2bz);
        a1bw=fmaf(pf5.w,w1,a1bw); a2bw=fmaf(pf5.w,w2,a2bw);
        w1 = w1s[3]; w2 = w2s[3];
        a1ax=fmaf(pf6.x,w1,a1ax); a2ax=fmaf(pf6.x,w2,a2ax);
        a1ay=fmaf(pf6.y,w1,a1ay); a2ay=fmaf(pf6.y,w2,a2ay);
        a1az=fmaf(pf6.z,w1,a1az); a2az=fmaf(pf6.z,w2,a2az);
        a1aw=fmaf(pf6.w,w1,a1aw); a2aw=fmaf(pf6.w,w2,a2aw);
        a1bx=fmaf(pf7.x,w1,a1bx); a2bx=fmaf(pf7.x,w2,a2bx);
        a1by=fmaf(pf7.y,w1,a1by); a2by=fmaf(pf7.y,w2,a2by);
        a1bz=fmaf(pf7.z,w1,a1bz); a2bz=fmaf(pf7.z,w2,a2bz);
        a1bw=fmaf(pf7.w,w1,a1bw); a2bw=fmaf(pf7.w,w2,a2bw);
        gBeg = fbase + 4;
    } else {
        // consume 2 prefetched m-row pairs (weights w[0], w[1])
        float w1, w2;
        w1 = w1s[0]; w2 = w2s[0];
        a1ax=fmaf(pf0.x,w1,a1ax); a2ax=fmaf(pf2.x,w2,a2ax);
        a1ay=fmaf(pf0.y,w1,a1ay); a2ay=fmaf(pf2.y,w2,a2ay);
        a1az=fmaf(pf0.z,w1,a1az); a2az=fmaf(pf2.z,w2,a2az);
        a1aw=fmaf(pf0.w,w1,a1aw); a2aw=fmaf(pf2.w,w2,a2aw);
        a1bx=fmaf(pf1.x,w1,a1bx); a2bx=fmaf(pf3.x,w2,a2bx);
        a1by=fmaf(pf1.y,w1,a1by); a2by=fmaf(pf3.y,w2,a2by);
        a1bz=fmaf(pf1.z,w1,a1bz); a2bz=fmaf(pf3.z,w2,a2bz);
        a1bw=fmaf(pf1.w,w1,a1bw); a2bw=fmaf(pf3.w,w2,a2bw);
        w1 = w1s[1]; w2 = w2s[1];
        a1ax=fmaf(pf4.x,w1,a1ax); a2ax=fmaf(pf6.x,w2,a2ax);
        a1ay=fmaf(pf4.y,w1,a1ay); a2ay=fmaf(pf6.y,w2,a2ay);
        a1az=fmaf(pf4.z,w1,a1az); a2az=fmaf(pf6.z,w2,a2az);
        a1aw=fmaf(pf4.w,w1,a1aw); a2aw=fmaf(pf6.w,w2,a2aw);
        a1bx=fmaf(pf5.x,w1,a1bx); a2bx=fmaf(pf7.x,w2,a2bx);
        a1by=fmaf(pf5.y,w1,a1by); a2by=fmaf(pf7.y,w2,a2by);
        a1bz=fmaf(pf5.z,w1,a1bz); a2bz=fmaf(pf7.z,w2,a2bz);
        a1bw=fmaf(pf5.w,w1,a1bw); a2bw=fmaf(pf7.w,w2,a2bw);
        mBeg = fM_beg + 2;
    }

    // --- G portion of this slice (steady state, unchanged) ---
#pragma unroll 4
    for (int f = gBeg; f < fG_end; ++f) {
        const float* row = Gb + (size_t)f * T_;
        float4 ga = ldg_stream(row);
        float4 gb = ldg_stream(row + HALF_T);
        float w1 = w1s[f - fbase];
        float w2 = w2s[f - fbase];
        a1ax = fmaf(ga.x, w1, a1ax);  a2ax = fmaf(ga.x, w2, a2ax);
        a1ay = fmaf(ga.y, w1, a1ay);  a2ay = fmaf(ga.y, w2, a2ay);
        a1az = fmaf(ga.z, w1, a1az);  a2az = fmaf(ga.z, w2, a2az);
        a1aw = fmaf(ga.w, w1, a1aw);  a2aw = fmaf(ga.w, w2, a2aw);
        a1bx = fmaf(gb.x, w1, a1bx);  a2bx = fmaf(gb.x, w2, a2bx);
        a1by = fmaf(gb.y, w1, a1by);  a2by = fmaf(gb.y, w2, a2by);
        a1bz = fmaf(gb.z, w1, a1bz);  a2bz = fmaf(gb.z, w2, a2bz);
        a1bw = fmaf(gb.w, w1, a1bw);  a2bw = fmaf(gb.w, w2, a2bw);
    }

    // --- m portion of this slice (steady state, unchanged) ---
#pragma unroll 4
    for (int f = mBeg; f < fM_end; ++f) {
        const int fm = f - FG;
        const float* r1 = M1b + (size_t)fm * T_;
        const float* r2 = M2b + (size_t)fm * T_;
        float4 v1a = ldg_stream(r1);
        float4 v1b = ldg_stream(r1 + HALF_T);
        float4 v2a = ldg_stream(r2);
        float4 v2b = ldg_stream(r2 + HALF_T);
        float w1 = w1s[f - fbase];
        float w2 = w2s[f - fbase];
        a1ax = fmaf(v1a.x, w1, a1ax);  a2ax = fmaf(v2a.x, w2, a2ax);
        a1ay = fmaf(v1a.y, w1, a1ay);  a2ay = fmaf(v2a.y, w2, a2ay);
        a1az = fmaf(v1a.z, w1, a1az);  a2az = fmaf(v2a.z, w2, a2az);
        a1aw = fmaf(v1a.w, w1, a1aw);  a2aw = fmaf(v2a.w, w2, a2aw);
        a1bx = fmaf(v1b.x, w1, a1bx);  a2bx = fmaf(v2b.x, w2, a2bx);
        a1by = fmaf(v1b.y, w1, a1by);  a2by = fmaf(v2b.y, w2, a2by);
        a1bz = fmaf(v1b.z, w1, a1bz);  a2bz = fmaf(v2b.z, w2, a2bz);
        a1bw = fmaf(v1b.w, w1, a1bw);  a2bw = fmaf(v2b.w, w2, a2bw);
    }

    // Accumulate into the logits scratch: [b][head][t]
    float* L1 = g_logits + ((size_t)b * 2 + 0) * T_ + t0;
    float* L2 = g_logits + ((size_t)b * 2 + 1) * T_ + t0;
    redg_add4(L1,          a1ax, a1ay, a1az, a1aw);
    redg_add4(L1 + HALF_T, a1bx, a1by, a1bz, a1bw);
    redg_add4(L2,          a2ax, a2ay, a2az, a2aw);
    redg_add4(L2 + HALF_T, a2bx, a2by, a2bz, a2bw);

    // ---- last-block-done fused softmax tail ----
    __threadfence();
    __syncthreads();
    __shared__ int s_last;
    if (threadIdx.x == 0)
        s_last = (atomicAdd(&g_count[b], 1) == BLOCKS_PER_B - 1);
    __syncthreads();
    if (!s_last) return;
    __threadfence();   // acquire: all 32 blocks' contributions now visible

    const int tid = threadIdx.x;
    const int wid = tid >> 5, lid = tid & 31;
    __shared__ float red[4];

    for (int head = 0; head < 2; ++head) {
        float* srow = g_logits + ((size_t)b * 2 + head) * T_;
        float* orow = out      + ((size_t)b * 2 + head) * T_;

        float4 v[4];
#pragma unroll
        for (int c = 0; c < 4; ++c)
            v[c] = ldg_cg4(&srow[c * 512 + tid * 4]);   // L2-direct

        float mx = -3.402823466e+38f;
#pragma unroll
        for (int c = 0; c < 4; ++c)
            mx = fmaxf(mx, fmaxf(fmaxf(v[c].x, v[c].y), fmaxf(v[c].z, v[c].w)));
#pragma unroll
        for (int o = 16; o > 0; o >>= 1)
            mx = fmaxf(mx, __shfl_xor_sync(0xffffffffu, mx, o));
        if (lid == 0) red[wid] = mx;
        __syncthreads();
        mx = fmaxf(fmaxf(red[0], red[1]), fmaxf(red[2], red[3]));
        __syncthreads();

        float sum = 0.f;
#pragma unroll
        for (int c = 0; c < 4; ++c) {
            v[c].x = __expf(v[c].x - mx); v[c].y = __expf(v[c].y - mx);
            v[c].z = __expf(v[c].z - mx); v[c].w = __expf(v[c].w - mx);
            sum += v[c].x + v[c].y + v[c].z + v[c].w;
        }
#pragma unroll
        for (int o = 16; o > 0; o >>= 1)
            sum += __shfl_xor_sync(0xffffffffu, sum, o);
        if (lid == 0) red[wid] = sum;
        __syncthreads();
        const float inv = 1.0f / (red[0] + red[1] + red[2] + red[3]);
        __syncthreads();

#pragma unroll
        for (int c = 0; c < 4; ++c) {
            *(float4*)&orow[c * 512 + tid * 4] =
                make_float4(v[c].x * inv, v[c].y * inv, v[c].z * inv, v[c].w * inv);
            *(float4*)&srow[c * 512 + tid * 4] = make_float4(0.f, 0.f, 0.f, 0.f);
        }
    }

    if (tid == 0) g_count[b] = 0;   // reset counter for next call/replay
}

extern "C" void kernel_launch(void* const* d_in, const int* in_sizes, int n_in,
                              void* d_out, int out_size) {
    const float* G   = (const float*)d_in[0];
    const float* m1  = (const float*)d_in[1];
    const float* m2  = (const float*)d_in[2];
    const float* wp1 = (const float*)d_in[3];
    const float* wp2 = (const float*)d_in[4];
    float* out = (float*)d_out;

    dim3 grid(T_ / TILE_T, B_, NSLICE);   // (2, 32, 16) = 1024 blocks
    dot_kernel<<<grid, THREADS>>>(G, m1, m2, wp1, wp2, out);
}